// round 14
// baseline (speedup 1.0000x reference)
#include <cuda_runtime.h>
#include <cuda_bf16.h>
#include <math.h>
#include <stdint.h>

// Problem constants: B=8, N=2048, M=2048, C=512
#define NB 8
#define NN 2048
#define MM 2048
#define CC 512

typedef __nv_bfloat16 bf16;

// ---------------- scratch (__device__ globals; no allocations allowed) -----
__device__ float g_attn  [(size_t)NB*NN*MM];               // fp32 raw scores
__device__ bf16  g_attn_h[(size_t)NB*NN*MM];
__device__ bf16  g_dec_h [(size_t)NB*NN*CC], g_dec_l[(size_t)NB*NN*CC];
__device__ bf16  g_enc_h [(size_t)NB*MM*CC], g_enc_l[(size_t)NB*MM*CC];
__device__ bf16  g_v_h   [(size_t)NB*MM*CC];
__device__ bf16  g_g_h   [(size_t)NB*NN*CC], g_g_l  [(size_t)NB*NN*CC];
__device__ bf16  g_h_h   [(size_t)NB*NN*CC], g_h_l  [(size_t)NB*NN*CC];
__device__ bf16  g_Wv_h  [CC*CC], g_Wv_l[CC*CC];
__device__ bf16  g_W1_h  [CC*CC], g_W1_l[CC*CC];
__device__ bf16  g_W2_h  [CC*CC], g_W2_l[CC*CC];

// ---------------- baseline-PTX helpers (sm_80-class, legal in compute_103) --
__device__ __forceinline__ uint32_t smem_u32(const void* p) {
    uint32_t a;
    asm("{ .reg .u64 t; cvta.to.shared.u64 t, %1; cvt.u32.u64 %0, t; }"
        : "=r"(a) : "l"(p));
    return a;
}

__device__ __forceinline__ void cp16(uint32_t dst, const void* src) {
    asm volatile("cp.async.cg.shared.global [%0], [%1], 16;"
                 :: "r"(dst), "l"(src) : "memory");
}
__device__ __forceinline__ void cp_commit() {
    asm volatile("cp.async.commit_group;" ::: "memory");
}
__device__ __forceinline__ void cp_wait0() {
    asm volatile("cp.async.wait_group 0;" ::: "memory");
}
__device__ __forceinline__ void cp_wait1() {
    asm volatile("cp.async.wait_group 1;" ::: "memory");
}

__device__ __forceinline__ void ldsm_x4(uint32_t* a, uint32_t addr) {
    asm volatile("ldmatrix.sync.aligned.m8n8.x4.shared.b16 {%0,%1,%2,%3}, [%4];"
                 : "=r"(a[0]), "=r"(a[1]), "=r"(a[2]), "=r"(a[3]) : "r"(addr));
}
__device__ __forceinline__ void ldsm_x2t(uint32_t* b, uint32_t addr) {
    asm volatile("ldmatrix.sync.aligned.m8n8.x2.trans.shared.b16 {%0,%1}, [%2];"
                 : "=r"(b[0]), "=r"(b[1]) : "r"(addr));
}

__device__ __forceinline__ void mma16816(float* c, const uint32_t* a,
                                         const uint32_t* b) {
    asm volatile(
        "mma.sync.aligned.m16n8k16.row.col.f32.bf16.bf16.f32 "
        "{%0,%1,%2,%3}, {%4,%5,%6,%7}, {%8,%9}, {%0,%1,%2,%3};"
        : "+f"(c[0]), "+f"(c[1]), "+f"(c[2]), "+f"(c[3])
        : "r"(a[0]), "r"(a[1]), "r"(a[2]), "r"(a[3]), "r"(b[0]), "r"(b[1]));
}

// ---------------- smem layout (k-tile = 64) --------------------------------
// A     : 128 rows x (64k*2B=128 +16 pad -> 144B)         = 18432B / matrix
// B NT  : 256 rows x 144B                                  = 36864B / matrix
// B NN  : 64 k-rows x (256n*2B=512 +16 pad -> 528B)        = 33792B / matrix
// Stage = A(h[,l]) + B(h[,l]); 2 stages.

// ---------------- split-bf16 tensor GEMM (mma.sync, 128x256 tile) ----------
// 512 threads, 16 warps, warp tile 64x32 (4 warps per SMSP for latency hiding)
// D tile [128,256] of A[M,K] * op(B), fp32 accum.
// SPLIT_A/SPLIT_B: 3 MMAs (AhBh+AhBl+AlBh) when both; 1 when neither.
// TRANS_B=true : B stored [n][k] K-major (NT).
// TRANS_B=false: B stored [k][n] n-major (NN), ldmatrix.trans.
// EPI: 0=bias+split(bf16 h/l out)  1=plain fp32 store (raw scores)
//      2=gate (split out = aux[r,c]*(1+tanh(acc)))
//      3=relu(bias) split           4=bias -> fp32 out
//      5=bias -> bf16 hi-only out
template <int EPI, bool TRANS_B, bool SPLIT_A, bool SPLIT_B>
__global__ __launch_bounds__(512, 1) void tc_gemm(
    const bf16* __restrict__ Ah, const bf16* __restrict__ Al,
    const bf16* __restrict__ Bh, const bf16* __restrict__ Bl,
    float* __restrict__ outF, bf16* __restrict__ outH, bf16* __restrict__ outL,
    const float* __restrict__ aux,
    int K, int ldB, int ldOut, long sA, long sB, long sOut, long sAux)
{
    constexpr uint32_t ASZ = 18432u;
    constexpr uint32_t BSZ = TRANS_B ? 36864u : 33792u;
    constexpr uint32_t ACNT = SPLIT_A ? 2u : 1u;
    constexpr uint32_t BCNT = SPLIT_B ? 2u : 1u;
    constexpr uint32_t BOFF = ASZ * ACNT;
    constexpr uint32_t STG  = BOFF + BCNT * BSZ;
    extern __shared__ char smem[];
    const uint32_t sb = smem_u32(smem);

    const int tid  = threadIdx.x;
    const int lane = tid & 31;
    const int wid  = tid >> 5;          // 0..15
    const int wr   = wid >> 3;          // 0..1 : 64 rows each
    const int wc   = wid & 7;           // 0..7 : 32 cols each
    const int bz   = blockIdx.z;

    Ah += (size_t)bz * sA;
    if (SPLIT_A) Al += (size_t)bz * sA;
    Bh += (size_t)bz * sB;
    if (SPLIT_B) Bl += (size_t)bz * sB;
    if (outF) outF += (size_t)bz * sOut;
    if (outH) outH += (size_t)bz * sOut;
    if (outL) outL += (size_t)bz * sOut;
    aux += (size_t)bz * sAux;

    const int brow = blockIdx.y * 128;
    const int bcol = blockIdx.x * 256;

    float acc[4][4][4];
#pragma unroll
    for (int mi = 0; mi < 4; mi++)
#pragma unroll
        for (int ni = 0; ni < 4; ni++)
#pragma unroll
            for (int q = 0; q < 4; q++) acc[mi][ni][q] = 0.f;

    const int nK = K >> 6;

    // ---- async tile loader for stage i (k-tile 64, 512 threads) ------------
    auto issue = [&](int i) {
        const int s  = i & 1;
        const int k0 = i << 6;
        const uint32_t base = sb + s * STG;
        // A: 128 rows x 128B -> 1024 x 16B chunks per matrix
#pragma unroll
        for (int j = 0; j < 2; j++) {
            int id = tid + 512 * j;
            int r = id >> 3, cs = id & 7;
            uint32_t so = (uint32_t)(r * 144 + cs * 16);
            cp16(base + so, Ah + (size_t)(brow + r) * K + k0 + cs * 8);
            if (SPLIT_A)
                cp16(base + ASZ + so, Al + (size_t)(brow + r) * K + k0 + cs * 8);
        }
        if (TRANS_B) {
            // B NT: 256 rows x 128B -> 2048 chunks per matrix
#pragma unroll
            for (int j = 0; j < 4; j++) {
                int id = tid + 512 * j;
                int r = id >> 3, cs = id & 7;
                uint32_t so = (uint32_t)(r * 144 + cs * 16);
                cp16(base + BOFF + so, Bh + (size_t)(bcol + r) * K + k0 + cs * 8);
                if (SPLIT_B)
                    cp16(base + BOFF + BSZ + so,
                         Bl + (size_t)(bcol + r) * K + k0 + cs * 8);
            }
        } else {
            // B NN: 64 k-rows x 512B -> 2048 chunks per matrix
#pragma unroll
            for (int j = 0; j < 4; j++) {
                int id = tid + 512 * j;
                int r = id >> 5, cs = id & 31;
                uint32_t so = (uint32_t)(r * 528 + cs * 16);
                cp16(base + BOFF + so, Bh + (size_t)(k0 + r) * ldB + bcol + cs * 8);
                if (SPLIT_B)
                    cp16(base + BOFF + BSZ + so,
                         Bl + (size_t)(k0 + r) * ldB + bcol + cs * 8);
            }
        }
        cp_commit();
    };

    issue(0);

    for (int i = 0; i < nK; i++) {
        if (i + 1 < nK) { issue(i + 1); cp_wait1(); }
        else            { cp_wait0(); }
        __syncthreads();

        const uint32_t base = sb + (i & 1) * STG;
        const uint32_t aHb = base, aLb = base + ASZ;
        const uint32_t bHb = base + BOFF, bLb = bHb + BSZ;

#pragma unroll
        for (int ks = 0; ks < 4; ks++) {
            const int kb = ks * 32;            // byte offset of this k16 chunk
            uint32_t ah[4][4], al[4][4];
#pragma unroll
            for (int mi = 0; mi < 4; mi++) {
                uint32_t off = (uint32_t)((wr * 64 + mi * 16 + (lane & 15)) * 144
                                          + kb + (lane >> 4) * 16);
                ldsm_x4(ah[mi], aHb + off);
                if (SPLIT_A) ldsm_x4(al[mi], aLb + off);
            }
            if (TRANS_B) {
                uint32_t bh[2][4], bl[2][4];
#pragma unroll
                for (int p = 0; p < 2; p++) {
                    int row = wc * 32 + p * 16 + (lane & 7)
                              + ((lane >> 4) & 1) * 8;
                    uint32_t off = (uint32_t)(row * 144 + kb
                                              + ((lane >> 3) & 1) * 16);
                    ldsm_x4(bh[p], bHb + off);
                    if (SPLIT_B) ldsm_x4(bl[p], bLb + off);
                }
#pragma unroll
                for (int mi = 0; mi < 4; mi++)
#pragma unroll
                    for (int p = 0; p < 2; p++)
#pragma unroll
                        for (int q = 0; q < 2; q++) {
                            float* c = acc[mi][p * 2 + q];
                            mma16816(c, ah[mi], &bh[p][q * 2]);
                            if (SPLIT_B) mma16816(c, ah[mi], &bl[p][q * 2]);
                            if (SPLIT_A) mma16816(c, al[mi], &bh[p][q * 2]);
                        }
            } else {
                uint32_t bh[4][2], bl[4][2];
#pragma unroll
                for (int t = 0; t < 4; t++) {
                    uint32_t off = (uint32_t)((ks * 16 + (lane & 15)) * 528
                                              + (wc * 32 + t * 8) * 2);
                    ldsm_x2t(bh[t], bHb + off);
                    if (SPLIT_B) ldsm_x2t(bl[t], bLb + off);
                }
#pragma unroll
                for (int mi = 0; mi < 4; mi++)
#pragma unroll
                    for (int t = 0; t < 4; t++) {
                        float* c = acc[mi][t];
                        mma16816(c, ah[mi], bh[t]);
                        if (SPLIT_B) mma16816(c, ah[mi], bl[t]);
                        if (SPLIT_A) mma16816(c, al[mi], bh[t]);
                    }
            }
        }
        __syncthreads();
    }

    // ---------------- epilogue ----------------------------------------------
    const int r_base = brow + wr * 64 + (lane >> 2);
    const int c_base = bcol + wc * 32 + (lane & 3) * 2;

#pragma unroll
    for (int mi = 0; mi < 4; mi++) {
#pragma unroll
        for (int half = 0; half < 2; half++) {
            const int r = r_base + mi * 16 + half * 8;
#pragma unroll
            for (int ni = 0; ni < 4; ni++) {
                const int c = c_base + ni * 8;
                float v0 = acc[mi][ni][half * 2 + 0];
                float v1 = acc[mi][ni][half * 2 + 1];

                if constexpr (EPI == 1) {            // raw scores -> fp32
                    float2 o; o.x = v0; o.y = v1;
                    *(float2*)(outF + (size_t)r * ldOut + c) = o;
                } else if constexpr (EPI == 4) {     // + bias -> fp32
                    float2 o; o.x = v0 + aux[c]; o.y = v1 + aux[c + 1];
                    *(float2*)(outF + (size_t)r * ldOut + c) = o;
                } else if constexpr (EPI == 5) {     // + bias -> bf16 hi only
                    v0 += aux[c]; v1 += aux[c + 1];
                    __nv_bfloat162 h2;
                    h2.x = __float2bfloat16(v0);
                    h2.y = __float2bfloat16(v1);
                    *(__nv_bfloat162*)(outH + (size_t)r * ldOut + c) = h2;
                } else {
                    if constexpr (EPI == 0) {        // + bias, split
                        v0 += aux[c]; v1 += aux[c + 1];
                    } else if constexpr (EPI == 3) { // relu(+bias), split
                        v0 = fmaxf(v0 + aux[c], 0.f);
                        v1 = fmaxf(v1 + aux[c + 1], 0.f);
                    } else {                         // EPI 2: gate, split
                        const float2 d = *(const float2*)(aux + (size_t)r * ldOut + c);
                        v0 = d.x * (1.f + tanhf(v0));
                        v1 = d.y * (1.f + tanhf(v1));
                    }
                    __nv_bfloat162 h2, l2;
                    h2.x = __float2bfloat16(v0);
                    h2.y = __float2bfloat16(v1);
                    l2.x = __float2bfloat16(v0 - __bfloat162float(h2.x));
                    l2.y = __float2bfloat16(v1 - __bfloat162float(h2.y));
                    *(__nv_bfloat162*)(outH + (size_t)r * ldOut + c) = h2;
                    *(__nv_bfloat162*)(outL + (size_t)r * ldOut + c) = l2;
                }
            }
        }
    }
}

// ---------------- fp32 -> bf16 hi/lo split ---------------------------------
__global__ __launch_bounds__(256) void split4_kernel(
    const float* __restrict__ x, bf16* __restrict__ h, bf16* __restrict__ l,
    int n4)
{
    int i = blockIdx.x * 256 + threadIdx.x;
    if (i >= n4) return;
    float4 v = ((const float4*)x)[i];
    float a[4] = {v.x, v.y, v.z, v.w};
    __nv_bfloat162* hp = (__nv_bfloat162*)h;
    __nv_bfloat162* lp = (__nv_bfloat162*)l;
#pragma unroll
    for (int p = 0; p < 2; p++) {
        __nv_bfloat162 h2, l2;
        h2.x = __float2bfloat16(a[p * 2 + 0]);
        h2.y = __float2bfloat16(a[p * 2 + 1]);
        l2.x = __float2bfloat16(a[p * 2 + 0] - __bfloat162float(h2.x));
        l2.y = __float2bfloat16(a[p * 2 + 1] - __bfloat162float(h2.y));
        hp[i * 2 + p] = h2;
        lp[i * 2 + p] = l2;
    }
}

// ---------------- masked softmax (mask folded in) + bf16 out ----------------
// s = raw * mask ; zeros participate in softmax; re-zero where s == 0.
__global__ __launch_bounds__(256) void softmax_kernel(
    const float* __restrict__ raw, const float* __restrict__ mask,
    bf16* __restrict__ oh)
{
    const size_t row = blockIdx.x;
    const float* p = raw + row * 2048;
    const float* m = mask + row * 2048;
    const int tid = threadIdx.x;
    const int lane = tid & 31, wrp = tid >> 5;

    __shared__ float red[8];

    float vals[8];
    float mx = -1e30f;
#pragma unroll
    for (int j = 0; j < 8; j++) {
        vals[j] = p[tid + 256 * j] * m[tid + 256 * j];
        mx = fmaxf(mx, vals[j]);
    }
#pragma unroll
    for (int o = 16; o > 0; o >>= 1)
        mx = fmaxf(mx, __shfl_xor_sync(0xFFFFFFFFu, mx, o));
    if (lane == 0) red[wrp] = mx;
    __syncthreads();
    mx = red[0];
#pragma unroll
    for (int w = 1; w < 8; w++) mx = fmaxf(mx, red[w]);
    __syncthreads();

    float ex[8], sum = 0.f;
#pragma unroll
    for (int j = 0; j < 8; j++) { ex[j] = __expf(vals[j] - mx); sum += ex[j]; }
#pragma unroll
    for (int o = 16; o > 0; o >>= 1)
        sum += __shfl_xor_sync(0xFFFFFFFFu, sum, o);
    if (lane == 0) red[wrp] = sum;
    __syncthreads();
    sum = red[0];
#pragma unroll
    for (int w = 1; w < 8; w++) sum += red[w];
    const float inv = 1.f / sum;

#pragma unroll
    for (int j = 0; j < 8; j++) {
        const size_t idx = row * 2048 + tid + 256 * j;
        float w = (vals[j] != 0.f) ? ex[j] * inv : 0.f;
        oh[idx] = __float2bfloat16(w);
    }
}

// ---------------- launch ----------------------------------------------------
extern "C" void kernel_launch(void* const* d_in, const int* in_sizes, int n_in,
                              void* d_out, int out_size)
{
    const float* dec   = (const float*)d_in[0];
    const float* enc   = (const float*)d_in[1];
    const float* trans = (const float*)d_in[2];
    const float* Wv    = (const float*)d_in[3];
    const float* bv    = (const float*)d_in[4];
    const float* W1    = (const float*)d_in[5];
    const float* b1    = (const float*)d_in[6];
    const float* W2    = (const float*)d_in[7];
    const float* b2    = (const float*)d_in[8];
    float* out = (float*)d_out;

    float* pattn;
    bf16 *pattn_h, *pdec_h, *pdec_l, *penc_h, *penc_l;
    bf16 *pv_h, *pg_h, *pg_l, *ph_h, *ph_l;
    bf16 *pWv_h, *pWv_l, *pW1_h, *pW1_l, *pW2_h, *pW2_l;
    cudaGetSymbolAddress((void**)&pattn,   g_attn);
    cudaGetSymbolAddress((void**)&pattn_h, g_attn_h);
    cudaGetSymbolAddress((void**)&pdec_h,  g_dec_h);
    cudaGetSymbolAddress((void**)&pdec_l,  g_dec_l);
    cudaGetSymbolAddress((void**)&penc_h,  g_enc_h);
    cudaGetSymbolAddress((void**)&penc_l,  g_enc_l);
    cudaGetSymbolAddress((void**)&pv_h,    g_v_h);
    cudaGetSymbolAddress((void**)&pg_h,    g_g_h);
    cudaGetSymbolAddress((void**)&pg_l,    g_g_l);
    cudaGetSymbolAddress((void**)&ph_h,    g_h_h);
    cudaGetSymbolAddress((void**)&ph_l,    g_h_l);
    cudaGetSymbolAddress((void**)&pWv_h,   g_Wv_h);
    cudaGetSymbolAddress((void**)&pWv_l,   g_Wv_l);
    cudaGetSymbolAddress((void**)&pW1_h,   g_W1_h);
    cudaGetSymbolAddress((void**)&pW1_l,   g_W1_l);
    cudaGetSymbolAddress((void**)&pW2_h,   g_W2_h);
    cudaGetSymbolAddress((void**)&pW2_l,   g_W2_l);

    // dynamic smem (2 stages, k64):
    // NT  split/split : 2*(2*18432 + 2*36864) = 221184
    // NN  split/split : 2*(2*18432 + 2*33792) = 208896
    // NN  uns/uns     : 2*(  18432 +   33792) = 104448
    const int SM_NT = 221184, SM_NN = 208896, SM_NN_11 = 104448;
    cudaFuncSetAttribute((const void*)tc_gemm<5, false, true , true >, cudaFuncAttributeMaxDynamicSharedMemorySize, SM_NN);
    cudaFuncSetAttribute((const void*)tc_gemm<1, true , true , true >, cudaFuncAttributeMaxDynamicSharedMemorySize, SM_NT);
    cudaFuncSetAttribute((const void*)tc_gemm<2, false, false, false>, cudaFuncAttributeMaxDynamicSharedMemorySize, SM_NN_11);
    cudaFuncSetAttribute((const void*)tc_gemm<3, false, true , true >, cudaFuncAttributeMaxDynamicSharedMemorySize, SM_NN);
    cudaFuncSetAttribute((const void*)tc_gemm<4, false, true , true >, cudaFuncAttributeMaxDynamicSharedMemorySize, SM_NN);

    const long NC  = (long)NN * CC;   // 2048*512
    const long NMs = (long)NN * MM;   // 2048*2048

    // splits
    const int n4i = NB * NN * CC / 4;
    split4_kernel<<<(n4i + 255) / 256, 256>>>(dec, pdec_h, pdec_l, n4i);
    split4_kernel<<<(n4i + 255) / 256, 256>>>(enc, penc_h, penc_l, n4i);
    const int n4w = CC * CC / 4;
    split4_kernel<<<(n4w + 255) / 256, 256>>>(Wv, pWv_h, pWv_l, n4w);
    split4_kernel<<<(n4w + 255) / 256, 256>>>(W1, pW1_h, pW1_l, n4w);
    split4_kernel<<<(n4w + 255) / 256, 256>>>(W2, pW2_h, pW2_l, n4w);

    // K1: v = enc @ Wv + bv (NN, 3-MMA split) -> bf16 hi only
    tc_gemm<5, false, true, true><<<dim3(2, 128, 1), 512, SM_NN>>>(
        penc_h, penc_l, pWv_h, pWv_l, nullptr, pv_h, nullptr, bv,
        512, 512, 512, 0, 0, 0, 0);

    // K2: raw scores = dec @ enc^T (NT, 3-MMA split) -> fp32
    tc_gemm<1, true, true, true><<<dim3(8, 16, 8), 512, SM_NT>>>(
        pdec_h, pdec_l, penc_h, penc_l, pattn, nullptr, nullptr, trans,
        512, 512, 2048, NC, NC, NMs, NMs);

    // K3: mask + nonstandard softmax -> bf16 attn (hi only)
    softmax_kernel<<<NB * NN, 256>>>(pattn, trans, pattn_h);

    // K4: g = dec * (1 + tanh(attn_h @ v_h)) (NN, 1-MMA) -> bf16 split
    tc_gemm<2, false, false, false><<<dim3(2, 16, 8), 512, SM_NN_11>>>(
        pattn_h, nullptr, pv_h, nullptr, nullptr, pg_h, pg_l, dec,
        2048, 512, 512, NMs, NC, NC, NC);

    // K5: h = relu(g @ W1 + b1) (NN, 3-MMA split) -> bf16 split
    tc_gemm<3, false, true, true><<<dim3(2, 128, 1), 512, SM_NN>>>(
        pg_h, pg_l, pW1_h, pW1_l, nullptr, ph_h, ph_l, b1,
        512, 512, 512, 0, 0, 0, 0);

    // K6: out = h @ W2 + b2 (NN, 3-MMA split) -> fp32
    tc_gemm<4, false, true, true><<<dim3(2, 128, 1), 512, SM_NN>>>(
        ph_h, ph_l, pW2_h, pW2_l, out, nullptr, nullptr, b2,
        512, 512, 512, 0, 0, 0, 0);
}